// round 2
// baseline (speedup 1.0000x reference)
#include <cuda_runtime.h>
#include <cuda_bf16.h>
#include <math.h>

// Fixed problem shapes (from reference setup_inputs)
#define N_FEAT   256
#define D_DIM    512
#define Q_BANK   2048
#define C_CLS    1000
#define IMG_ELEM 150528            // 3*224*224
#define IMG_V4   (IMG_ELEM / 4)    // 37632 float4 per image
#define K_NB     4

// Output layout (float32, concatenated in reference return order)
#define O_LABELS 0
#define O_PROBS  (O_LABELS + N_FEAT)                       // 256
#define O_IMAGES (O_PROBS + (size_t)N_FEAT * C_CLS)        // 256256
#define O_GRADS  (O_IMAGES + (size_t)N_FEAT * IMG_ELEM)    // 38791424

// Device scratch (no allocations allowed)
__device__ float g_norm_bank[Q_BANK];
__device__ float g_norm_feat[N_FEAT];
__device__ float g_dist[(size_t)N_FEAT * Q_BANK];
__device__ int   g_idx[N_FEAT * K_NB];

// ---------------------------------------------------------------------------
// Kernel 1: row L2 norms for bank_features (2048 rows) and features (256 rows)
// one warp per row
// ---------------------------------------------------------------------------
__global__ void k_norms(const float* __restrict__ feats,
                        const float* __restrict__ bank)
{
    int warp = (blockIdx.x * blockDim.x + threadIdx.x) >> 5;
    int lane = threadIdx.x & 31;
    int total = Q_BANK + N_FEAT;
    if (warp >= total) return;

    const float* row;
    if (warp < Q_BANK) row = bank + (size_t)warp * D_DIM;
    else               row = feats + (size_t)(warp - Q_BANK) * D_DIM;

    float s = 0.f;
    const float4* r4 = (const float4*)row;
    #pragma unroll
    for (int i = lane; i < D_DIM / 4; i += 32) {
        float4 v = r4[i];
        s += v.x * v.x + v.y * v.y + v.z * v.z + v.w * v.w;
    }
    #pragma unroll
    for (int o = 16; o; o >>= 1) s += __shfl_xor_sync(0xffffffffu, s, o);

    if (lane == 0) {
        float n = fmaxf(sqrtf(s), 1e-12f);
        if (warp < Q_BANK) g_norm_bank[warp] = n;
        else               g_norm_feat[warp - Q_BANK] = n;
    }
}

// ---------------------------------------------------------------------------
// Kernel 2: distance matrix dist[n][q] = 1 - <xn, yq>/(|x||y|)
// grid: (N_FEAT/8, 4). Each block handles 8 feature rows x 512 bank rows.
// 256 threads = 8 warps; warp w walks bank rows w, w+8, ...
// ---------------------------------------------------------------------------
__global__ void k_dist(const float* __restrict__ feats,
                       const float* __restrict__ bank)
{
    __shared__ float4 sfeat[8][D_DIM / 4];   // normalized feature rows

    int fbase = blockIdx.x * 8;
    int tid = threadIdx.x;
    // cooperative load + normalize (divide by feature norm once)
    for (int i = tid; i < 8 * (D_DIM / 4); i += blockDim.x) {
        int j = i / (D_DIM / 4);
        int k = i % (D_DIM / 4);
        float4 v = ((const float4*)(feats + (size_t)(fbase + j) * D_DIM))[k];
        float inv = 1.0f / g_norm_feat[fbase + j];
        v.x *= inv; v.y *= inv; v.z *= inv; v.w *= inv;
        sfeat[j][k] = v;
    }
    __syncthreads();

    int warp = tid >> 5;
    int lane = tid & 31;
    int rbeg = blockIdx.y * (Q_BANK / 4);
    int rend = rbeg + (Q_BANK / 4);

    for (int r = rbeg + warp; r < rend; r += 8) {
        float acc[8] = {0.f, 0.f, 0.f, 0.f, 0.f, 0.f, 0.f, 0.f};
        const float4* brow = (const float4*)(bank + (size_t)r * D_DIM);
        #pragma unroll
        for (int k = lane; k < D_DIM / 4; k += 32) {
            float4 b = brow[k];
            #pragma unroll
            for (int j = 0; j < 8; j++) {
                float4 f = sfeat[j][k];
                acc[j] += b.x * f.x + b.y * f.y + b.z * f.z + b.w * f.w;
            }
        }
        #pragma unroll
        for (int j = 0; j < 8; j++) {
            float a = acc[j];
            #pragma unroll
            for (int o = 16; o; o >>= 1) a += __shfl_xor_sync(0xffffffffu, a, o);
            if (lane == 0) {
                float d = 1.0f - a / g_norm_bank[r];
                g_dist[(size_t)(fbase + j) * Q_BANK + r] = d;
            }
        }
    }
}

// ---------------------------------------------------------------------------
// Kernel 3: top-4 (largest distance) per feature row; tie -> lowest index
// one block (128 threads) per row, 4 iterative argmax passes
// ---------------------------------------------------------------------------
__global__ void k_topk()
{
    __shared__ float sval[128];
    __shared__ int   sidx[128];
    __shared__ int   picked[K_NB];

    int n = blockIdx.x;
    int tid = threadIdx.x;
    const float* row = g_dist + (size_t)n * Q_BANK;

    for (int p = 0; p < K_NB; p++) {
        float bv = -1e30f;
        int   bi = 0x7fffffff;
        for (int i = tid; i < Q_BANK; i += 128) {
            bool skip = false;
            for (int s = 0; s < p; s++) skip |= (picked[s] == i);
            if (skip) continue;
            float v = row[i];
            if (v > bv) { bv = v; bi = i; }   // ascending scan -> first occurrence wins
        }
        sval[tid] = bv; sidx[tid] = bi;
        __syncthreads();
        for (int o = 64; o; o >>= 1) {
            if (tid < o) {
                float ov = sval[tid + o]; int oi = sidx[tid + o];
                if (ov > sval[tid] || (ov == sval[tid] && oi < sidx[tid])) {
                    sval[tid] = ov; sidx[tid] = oi;
                }
            }
            __syncthreads();
        }
        if (tid == 0) { picked[p] = sidx[0]; g_idx[n * K_NB + p] = sidx[0]; }
        __syncthreads();
    }
}

// ---------------------------------------------------------------------------
// Kernel 4: pred_probs (mean of 4 bank_probs rows) + argmax label
//           + grads_m (mean of 4 bank_features rows)
// one block (256 threads) per feature row
// ---------------------------------------------------------------------------
__global__ void k_probs_grads(const float* __restrict__ bank,
                              const float* __restrict__ bprobs,
                              float* __restrict__ out)
{
    __shared__ float sval[256];
    __shared__ int   sidx[256];

    int n = blockIdx.x;
    int tid = threadIdx.x;
    int i0 = g_idx[n * K_NB + 0];
    int i1 = g_idx[n * K_NB + 1];
    int i2 = g_idx[n * K_NB + 2];
    int i3 = g_idx[n * K_NB + 3];

    // probs mean + local argmax
    float bv = -1e30f;
    int   bc = 0x7fffffff;
    float* oprobs = out + O_PROBS + (size_t)n * C_CLS;
    for (int c = tid; c < C_CLS; c += 256) {
        float v = 0.25f * (bprobs[(size_t)i0 * C_CLS + c] +
                           bprobs[(size_t)i1 * C_CLS + c] +
                           bprobs[(size_t)i2 * C_CLS + c] +
                           bprobs[(size_t)i3 * C_CLS + c]);
        oprobs[c] = v;
        if (v > bv) { bv = v; bc = c; }   // ascending -> first occurrence
    }
    sval[tid] = bv; sidx[tid] = bc;
    __syncthreads();
    for (int o = 128; o; o >>= 1) {
        if (tid < o) {
            float ov = sval[tid + o]; int oi = sidx[tid + o];
            if (ov > sval[tid] || (ov == sval[tid] && oi < sidx[tid])) {
                sval[tid] = ov; sidx[tid] = oi;
            }
        }
        __syncthreads();
    }
    if (tid == 0) out[O_LABELS + n] = (float)sidx[0];

    // grads mean
    float* ograds = out + O_GRADS + (size_t)n * D_DIM;
    for (int d = tid; d < D_DIM; d += 256) {
        float v = 0.25f * (bank[(size_t)i0 * D_DIM + d] +
                           bank[(size_t)i1 * D_DIM + d] +
                           bank[(size_t)i2 * D_DIM + d] +
                           bank[(size_t)i3 * D_DIM + d]);
        ograds[d] = v;
    }
}

// ---------------------------------------------------------------------------
// Kernel 5: pred_images = mean of 4 gathered image rows. Pure bandwidth.
// grid (IMG_V4/256 = 147, N_FEAT), 256 threads, float4 vectorized.
// ---------------------------------------------------------------------------
__global__ void k_images(const float* __restrict__ imgs,
                         float* __restrict__ out)
{
    int n = blockIdx.y;
    int t = blockIdx.x * blockDim.x + threadIdx.x;   // float4 index, < IMG_V4
    if (t >= IMG_V4) return;

    int i0 = __ldg(&g_idx[n * K_NB + 0]);
    int i1 = __ldg(&g_idx[n * K_NB + 1]);
    int i2 = __ldg(&g_idx[n * K_NB + 2]);
    int i3 = __ldg(&g_idx[n * K_NB + 3]);

    const float4* iv = (const float4*)imgs;
    float4 a = iv[(size_t)i0 * IMG_V4 + t];
    float4 b = iv[(size_t)i1 * IMG_V4 + t];
    float4 c = iv[(size_t)i2 * IMG_V4 + t];
    float4 d = iv[(size_t)i3 * IMG_V4 + t];

    float4 r;
    r.x = 0.25f * (a.x + b.x + c.x + d.x);
    r.y = 0.25f * (a.y + b.y + c.y + d.y);
    r.z = 0.25f * (a.z + b.z + c.z + d.z);
    r.w = 0.25f * (a.w + b.w + c.w + d.w);

    float4* ov = (float4*)(out + O_IMAGES);
    ov[(size_t)n * IMG_V4 + t] = r;
}

// ---------------------------------------------------------------------------
extern "C" void kernel_launch(void* const* d_in, const int* in_sizes, int n_in,
                              void* d_out, int out_size)
{
    const float* feats  = (const float*)d_in[0];   // (256, 512)
    const float* bank   = (const float*)d_in[1];   // (2048, 512)
    const float* bprobs = (const float*)d_in[2];   // (2048, 1000)
    const float* imgs   = (const float*)d_in[3];   // (2048, 3, 224, 224)
    float* out = (float*)d_out;

    {
        int warps = Q_BANK + N_FEAT;              // 2304 warps
        int threads = 256;
        int blocks = (warps * 32 + threads - 1) / threads;
        k_norms<<<blocks, threads>>>(feats, bank);
    }
    {
        dim3 grid(N_FEAT / 8, 4);                 // (32, 4)
        k_dist<<<grid, 256>>>(feats, bank);
    }
    k_topk<<<N_FEAT, 128>>>();
    k_probs_grads<<<N_FEAT, 256>>>(bank, bprobs, out);
    {
        dim3 grid((IMG_V4 + 255) / 256, N_FEAT);  // (147, 256)
        k_images<<<grid, 256>>>(imgs, out);
    }
}

// round 5
// speedup vs baseline: 1.1222x; 1.1222x over previous
#include <cuda_runtime.h>
#include <cuda_bf16.h>
#include <math.h>

// Fixed problem shapes (from reference setup_inputs)
#define N_FEAT   256
#define D_DIM    512
#define Q_BANK   2048
#define C_CLS    1000
#define IMG_ELEM 150528            // 3*224*224
#define IMG_V4   (IMG_ELEM / 4)    // 37632 float4 per image
#define K_NB     4

// Output layout (float32, concatenated in reference return order)
#define O_LABELS 0
#define O_PROBS  (O_LABELS + N_FEAT)                       // 256
#define O_IMAGES (O_PROBS + (size_t)N_FEAT * C_CLS)        // 256256
#define O_GRADS  (O_IMAGES + (size_t)N_FEAT * IMG_ELEM)    // 38791424

// Device scratch (no allocations allowed)
__device__ float g_norm_bank[Q_BANK];
__device__ float g_dist[(size_t)N_FEAT * Q_BANK];
__device__ int   g_idx[N_FEAT * K_NB];

// ---------------------------------------------------------------------------
// Kernel 1: row L2 norms for bank_features (2048 rows), one warp per row
// ---------------------------------------------------------------------------
__global__ void k_norms_bank(const float* __restrict__ bank)
{
    int warp = (blockIdx.x * blockDim.x + threadIdx.x) >> 5;
    int lane = threadIdx.x & 31;
    if (warp >= Q_BANK) return;

    const float4* r4 = (const float4*)(bank + (size_t)warp * D_DIM);
    float s = 0.f;
    #pragma unroll
    for (int i = lane; i < D_DIM / 4; i += 32) {
        float4 v = r4[i];
        s += v.x * v.x + v.y * v.y + v.z * v.z + v.w * v.w;
    }
    #pragma unroll
    for (int o = 16; o; o >>= 1) s += __shfl_xor_sync(0xffffffffu, s, o);
    if (lane == 0) g_norm_bank[warp] = fmaxf(sqrtf(s), 1e-12f);
}

// ---------------------------------------------------------------------------
// Kernel 2: distance matrix dist[n][q] = 1 - <xn, yq>/(|x||y|)
// grid: (N_FEAT/8, 8) = 256 CTAs. Each block: 8 feature rows x 256 bank rows.
// Feature norms computed in-block (warp j normalizes smem row j).
// ---------------------------------------------------------------------------
__global__ void k_dist(const float* __restrict__ feats,
                       const float* __restrict__ bank)
{
    __shared__ float4 sfeat[8][D_DIM / 4];   // feature rows (normalized in-place)

    int fbase = blockIdx.x * 8;
    int tid  = threadIdx.x;
    int warp = tid >> 5;
    int lane = tid & 31;

    // cooperative raw load
    for (int i = tid; i < 8 * (D_DIM / 4); i += blockDim.x) {
        int j = i / (D_DIM / 4);
        int k = i % (D_DIM / 4);
        sfeat[j][k] = ((const float4*)(feats + (size_t)(fbase + j) * D_DIM))[k];
    }
    __syncthreads();

    // warp j computes norm of row j and normalizes it
    {
        float s = 0.f;
        #pragma unroll
        for (int k = lane; k < D_DIM / 4; k += 32) {
            float4 v = sfeat[warp][k];
            s += v.x * v.x + v.y * v.y + v.z * v.z + v.w * v.w;
        }
        #pragma unroll
        for (int o = 16; o; o >>= 1) s += __shfl_xor_sync(0xffffffffu, s, o);
        float inv = 1.0f / fmaxf(sqrtf(s), 1e-12f);
        #pragma unroll
        for (int k = lane; k < D_DIM / 4; k += 32) {
            float4 v = sfeat[warp][k];
            v.x *= inv; v.y *= inv; v.z *= inv; v.w *= inv;
            sfeat[warp][k] = v;
        }
    }
    __syncthreads();

    const int ROWS_PER_BLK = Q_BANK / 8;     // 256
    int rbeg = blockIdx.y * ROWS_PER_BLK;
    int rend = rbeg + ROWS_PER_BLK;

    for (int r = rbeg + warp; r < rend; r += 8) {
        float acc[8] = {0.f, 0.f, 0.f, 0.f, 0.f, 0.f, 0.f, 0.f};
        const float4* brow = (const float4*)(bank + (size_t)r * D_DIM);
        #pragma unroll
        for (int k = lane; k < D_DIM / 4; k += 32) {
            float4 b = brow[k];
            #pragma unroll
            for (int j = 0; j < 8; j++) {
                float4 f = sfeat[j][k];
                acc[j] += b.x * f.x + b.y * f.y + b.z * f.z + b.w * f.w;
            }
        }
        float invbn = 1.0f / g_norm_bank[r];
        #pragma unroll
        for (int j = 0; j < 8; j++) {
            float a = acc[j];
            #pragma unroll
            for (int o = 16; o; o >>= 1) a += __shfl_xor_sync(0xffffffffu, a, o);
            if (lane == 0)
                g_dist[(size_t)(fbase + j) * Q_BANK + r] = 1.0f - a * invbn;
        }
    }
}

// ---------------------------------------------------------------------------
// Kernel 3: top-4 (largest distance) per feature row; tie -> lowest index
// one block (128 threads) per row, 4 iterative argmax passes
// ---------------------------------------------------------------------------
__global__ void k_topk()
{
    __shared__ float sval[128];
    __shared__ int   sidx[128];
    __shared__ int   picked[K_NB];

    int n = blockIdx.x;
    int tid = threadIdx.x;
    const float* row = g_dist + (size_t)n * Q_BANK;

    for (int p = 0; p < K_NB; p++) {
        float bv = -1e30f;
        int   bi = 0x7fffffff;
        for (int i = tid; i < Q_BANK; i += 128) {
            bool skip = false;
            for (int s = 0; s < p; s++) skip |= (picked[s] == i);
            if (skip) continue;
            float v = row[i];
            if (v > bv) { bv = v; bi = i; }   // ascending scan -> first occurrence wins
        }
        sval[tid] = bv; sidx[tid] = bi;
        __syncthreads();
        for (int o = 64; o; o >>= 1) {
            if (tid < o) {
                float ov = sval[tid + o]; int oi = sidx[tid + o];
                if (ov > sval[tid] || (ov == sval[tid] && oi < sidx[tid])) {
                    sval[tid] = ov; sidx[tid] = oi;
                }
            }
            __syncthreads();
        }
        if (tid == 0) { picked[p] = sidx[0]; g_idx[n * K_NB + p] = sidx[0]; }
        __syncthreads();
    }
}

// ---------------------------------------------------------------------------
// Kernel 4: pred_probs (mean of 4 bank_probs rows) + argmax label
//           + grads_m (mean of 4 bank_features rows)
// one block (256 threads) per feature row
// ---------------------------------------------------------------------------
__global__ void k_probs_grads(const float* __restrict__ bank,
                              const float* __restrict__ bprobs,
                              float* __restrict__ out)
{
    __shared__ float sval[256];
    __shared__ int   sidx[256];

    int n = blockIdx.x;
    int tid = threadIdx.x;
    int i0 = __ldg(&g_idx[n * K_NB + 0]);
    int i1 = __ldg(&g_idx[n * K_NB + 1]);
    int i2 = __ldg(&g_idx[n * K_NB + 2]);
    int i3 = __ldg(&g_idx[n * K_NB + 3]);

    // probs mean + local argmax
    float bv = -1e30f;
    int   bc = 0x7fffffff;
    float* oprobs = out + O_PROBS + (size_t)n * C_CLS;
    for (int c = tid; c < C_CLS; c += 256) {
        float v = 0.25f * (bprobs[(size_t)i0 * C_CLS + c] +
                           bprobs[(size_t)i1 * C_CLS + c] +
                           bprobs[(size_t)i2 * C_CLS + c] +
                           bprobs[(size_t)i3 * C_CLS + c]);
        oprobs[c] = v;
        if (v > bv) { bv = v; bc = c; }   // ascending -> first occurrence
    }
    sval[tid] = bv; sidx[tid] = bc;
    __syncthreads();
    for (int o = 128; o; o >>= 1) {
        if (tid < o) {
            float ov = sval[tid + o]; int oi = sidx[tid + o];
            if (ov > sval[tid] || (ov == sval[tid] && oi < sidx[tid])) {
                sval[tid] = ov; sidx[tid] = oi;
            }
        }
        __syncthreads();
    }
    if (tid == 0) out[O_LABELS + n] = (float)sidx[0];

    // grads mean
    float* ograds = out + O_GRADS + (size_t)n * D_DIM;
    for (int d = tid; d < D_DIM; d += 256) {
        float v = 0.25f * (bank[(size_t)i0 * D_DIM + d] +
                           bank[(size_t)i1 * D_DIM + d] +
                           bank[(size_t)i2 * D_DIM + d] +
                           bank[(size_t)i3 * D_DIM + d]);
        ograds[d] = v;
    }
}

// ---------------------------------------------------------------------------
// Kernel 5: pred_images = mean of 4 gathered image rows. Pure bandwidth.
// grid (N_FEAT, IMG_V4/256): blockIdx.x = n (fastest), blockIdx.y = slice.
// A wave of CTAs thus covers ONE 16KB slice of the bank across ALL features;
// the per-slice bank working set (2048 x 4KB per 256-thread chunk; ~32MB per
// concurrent window) stays L2-resident, so duplicate neighbor indices across
// features hit L2 instead of HBM.
// ---------------------------------------------------------------------------
__global__ void k_images(const float* __restrict__ imgs,
                         float* __restrict__ out)
{
    int n = blockIdx.x;
    int t = blockIdx.y * blockDim.x + threadIdx.x;   // float4 index, < IMG_V4

    int i0 = __ldg(&g_idx[n * K_NB + 0]);
    int i1 = __ldg(&g_idx[n * K_NB + 1]);
    int i2 = __ldg(&g_idx[n * K_NB + 2]);
    int i3 = __ldg(&g_idx[n * K_NB + 3]);

    const float4* iv = (const float4*)imgs;
    float4 a = __ldg(&iv[(size_t)i0 * IMG_V4 + t]);
    float4 b = __ldg(&iv[(size_t)i1 * IMG_V4 + t]);
    float4 c = __ldg(&iv[(size_t)i2 * IMG_V4 + t]);
    float4 d = __ldg(&iv[(size_t)i3 * IMG_V4 + t]);

    float4 r;
    r.x = 0.25f * (a.x + b.x + c.x + d.x);
    r.y = 0.25f * (a.y + b.y + c.y + d.y);
    r.z = 0.25f * (a.z + b.z + c.z + d.z);
    r.w = 0.25f * (a.w + b.w + c.w + d.w);

    float4* ov = (float4*)(out + O_IMAGES);
    ov[(size_t)n * IMG_V4 + t] = r;
}

// ---------------------------------------------------------------------------
extern "C" void kernel_launch(void* const* d_in, const int* in_sizes, int n_in,
                              void* d_out, int out_size)
{
    const float* feats  = (const float*)d_in[0];   // (256, 512)
    const float* bank   = (const float*)d_in[1];   // (2048, 512)
    const float* bprobs = (const float*)d_in[2];   // (2048, 1000)
    const float* imgs   = (const float*)d_in[3];   // (2048, 3, 224, 224)
    float* out = (float*)d_out;

    k_norms_bank<<<(Q_BANK * 32) / 256, 256>>>(bank);

    {
        dim3 grid(N_FEAT / 8, 8);                 // (32, 8) = 256 CTAs
        k_dist<<<grid, 256>>>(feats, bank);
    }
    k_topk<<<N_FEAT, 128>>>();
    k_probs_grads<<<N_FEAT, 256>>>(bank, bprobs, out);
    {
        dim3 grid(N_FEAT, IMG_V4 / 256);          // (256, 147), x = n fastest
        k_images<<<grid, 256>>>(imgs, out);
    }
}

// round 6
// speedup vs baseline: 1.1249x; 1.0024x over previous
#include <cuda_runtime.h>
#include <cuda_bf16.h>
#include <math.h>

// Fixed problem shapes (from reference setup_inputs)
#define N_FEAT   256
#define D_DIM    512
#define Q_BANK   2048
#define C_CLS    1000
#define IMG_ELEM 150528            // 3*224*224
#define IMG_V4   (IMG_ELEM / 4)    // 37632 float4 per image
#define K_NB     4

// Output layout (float32, concatenated in reference return order)
#define O_LABELS 0
#define O_PROBS  (O_LABELS + N_FEAT)                       // 256
#define O_IMAGES (O_PROBS + (size_t)N_FEAT * C_CLS)        // 256256
#define O_GRADS  (O_IMAGES + (size_t)N_FEAT * IMG_ELEM)    // 38791424

// Device scratch (no allocations allowed)
__device__ float g_norm_bank[Q_BANK];
__device__ float g_dist[(size_t)N_FEAT * Q_BANK];
__device__ int   g_idx[N_FEAT * K_NB];

// ---------------------------------------------------------------------------
// Kernel 1: row L2 norms for bank_features (2048 rows), one warp per row
// ---------------------------------------------------------------------------
__global__ void k_norms_bank(const float* __restrict__ bank)
{
    int warp = (blockIdx.x * blockDim.x + threadIdx.x) >> 5;
    int lane = threadIdx.x & 31;
    if (warp >= Q_BANK) return;

    const float4* r4 = (const float4*)(bank + (size_t)warp * D_DIM);
    float s = 0.f;
    #pragma unroll
    for (int i = lane; i < D_DIM / 4; i += 32) {
        float4 v = r4[i];
        s += v.x * v.x + v.y * v.y + v.z * v.z + v.w * v.w;
    }
    #pragma unroll
    for (int o = 16; o; o >>= 1) s += __shfl_xor_sync(0xffffffffu, s, o);
    if (lane == 0) g_norm_bank[warp] = fmaxf(sqrtf(s), 1e-12f);
}

// ---------------------------------------------------------------------------
// Kernel 2: distance matrix dist[n][q] = 1 - <xn, yq>/(|x||y|)
// grid: (N_FEAT/8, 8) = 256 CTAs. Each block: 8 feature rows x 256 bank rows.
// Feature norms computed in-block (warp j normalizes smem row j).
// ---------------------------------------------------------------------------
__global__ void k_dist(const float* __restrict__ feats,
                       const float* __restrict__ bank)
{
    __shared__ float4 sfeat[8][D_DIM / 4];   // feature rows (normalized in-place)

    int fbase = blockIdx.x * 8;
    int tid  = threadIdx.x;
    int warp = tid >> 5;
    int lane = tid & 31;

    // cooperative raw load
    for (int i = tid; i < 8 * (D_DIM / 4); i += blockDim.x) {
        int j = i / (D_DIM / 4);
        int k = i % (D_DIM / 4);
        sfeat[j][k] = ((const float4*)(feats + (size_t)(fbase + j) * D_DIM))[k];
    }
    __syncthreads();

    // warp j computes norm of row j and normalizes it
    {
        float s = 0.f;
        #pragma unroll
        for (int k = lane; k < D_DIM / 4; k += 32) {
            float4 v = sfeat[warp][k];
            s += v.x * v.x + v.y * v.y + v.z * v.z + v.w * v.w;
        }
        #pragma unroll
        for (int o = 16; o; o >>= 1) s += __shfl_xor_sync(0xffffffffu, s, o);
        float inv = 1.0f / fmaxf(sqrtf(s), 1e-12f);
        #pragma unroll
        for (int k = lane; k < D_DIM / 4; k += 32) {
            float4 v = sfeat[warp][k];
            v.x *= inv; v.y *= inv; v.z *= inv; v.w *= inv;
            sfeat[warp][k] = v;
        }
    }
    __syncthreads();

    const int ROWS_PER_BLK = Q_BANK / 8;     // 256
    int rbeg = blockIdx.y * ROWS_PER_BLK;
    int rend = rbeg + ROWS_PER_BLK;

    for (int r = rbeg + warp; r < rend; r += 8) {
        float acc[8] = {0.f, 0.f, 0.f, 0.f, 0.f, 0.f, 0.f, 0.f};
        const float4* brow = (const float4*)(bank + (size_t)r * D_DIM);
        #pragma unroll
        for (int k = lane; k < D_DIM / 4; k += 32) {
            float4 b = brow[k];
            #pragma unroll
            for (int j = 0; j < 8; j++) {
                float4 f = sfeat[j][k];
                acc[j] += b.x * f.x + b.y * f.y + b.z * f.z + b.w * f.w;
            }
        }
        float invbn = 1.0f / g_norm_bank[r];
        #pragma unroll
        for (int j = 0; j < 8; j++) {
            float a = acc[j];
            #pragma unroll
            for (int o = 16; o; o >>= 1) a += __shfl_xor_sync(0xffffffffu, a, o);
            if (lane == 0)
                g_dist[(size_t)(fbase + j) * Q_BANK + r] = 1.0f - a * invbn;
        }
    }
}

// ---------------------------------------------------------------------------
// Kernel 3: top-4 (largest distance) per feature row; tie -> lowest index
// one block (128 threads) per row, 4 iterative argmax passes
// ---------------------------------------------------------------------------
__global__ void k_topk()
{
    __shared__ float sval[128];
    __shared__ int   sidx[128];
    __shared__ int   picked[K_NB];

    int n = blockIdx.x;
    int tid = threadIdx.x;
    const float* row = g_dist + (size_t)n * Q_BANK;

    for (int p = 0; p < K_NB; p++) {
        float bv = -1e30f;
        int   bi = 0x7fffffff;
        for (int i = tid; i < Q_BANK; i += 128) {
            bool skip = false;
            for (int s = 0; s < p; s++) skip |= (picked[s] == i);
            if (skip) continue;
            float v = row[i];
            if (v > bv) { bv = v; bi = i; }   // ascending scan -> first occurrence wins
        }
        sval[tid] = bv; sidx[tid] = bi;
        __syncthreads();
        for (int o = 64; o; o >>= 1) {
            if (tid < o) {
                float ov = sval[tid + o]; int oi = sidx[tid + o];
                if (ov > sval[tid] || (ov == sval[tid] && oi < sidx[tid])) {
                    sval[tid] = ov; sidx[tid] = oi;
                }
            }
            __syncthreads();
        }
        if (tid == 0) { picked[p] = sidx[0]; g_idx[n * K_NB + p] = sidx[0]; }
        __syncthreads();
    }
}

// ---------------------------------------------------------------------------
// Kernel 4: pred_probs (mean of 4 bank_probs rows) + argmax label
//           + grads_m (mean of 4 bank_features rows)
// one block (256 threads) per feature row
// ---------------------------------------------------------------------------
__global__ void k_probs_grads(const float* __restrict__ bank,
                              const float* __restrict__ bprobs,
                              float* __restrict__ out)
{
    __shared__ float sval[256];
    __shared__ int   sidx[256];

    int n = blockIdx.x;
    int tid = threadIdx.x;
    int i0 = __ldg(&g_idx[n * K_NB + 0]);
    int i1 = __ldg(&g_idx[n * K_NB + 1]);
    int i2 = __ldg(&g_idx[n * K_NB + 2]);
    int i3 = __ldg(&g_idx[n * K_NB + 3]);

    // probs mean + local argmax
    float bv = -1e30f;
    int   bc = 0x7fffffff;
    float* oprobs = out + O_PROBS + (size_t)n * C_CLS;
    for (int c = tid; c < C_CLS; c += 256) {
        float v = 0.25f * (bprobs[(size_t)i0 * C_CLS + c] +
                           bprobs[(size_t)i1 * C_CLS + c] +
                           bprobs[(size_t)i2 * C_CLS + c] +
                           bprobs[(size_t)i3 * C_CLS + c]);
        oprobs[c] = v;
        if (v > bv) { bv = v; bc = c; }   // ascending -> first occurrence
    }
    sval[tid] = bv; sidx[tid] = bc;
    __syncthreads();
    for (int o = 128; o; o >>= 1) {
        if (tid < o) {
            float ov = sval[tid + o]; int oi = sidx[tid + o];
            if (ov > sval[tid] || (ov == sval[tid] && oi < sidx[tid])) {
                sval[tid] = ov; sidx[tid] = oi;
            }
        }
        __syncthreads();
    }
    if (tid == 0) out[O_LABELS + n] = (float)sidx[0];

    // grads mean
    float* ograds = out + O_GRADS + (size_t)n * D_DIM;
    for (int d = tid; d < D_DIM; d += 256) {
        float v = 0.25f * (bank[(size_t)i0 * D_DIM + d] +
                           bank[(size_t)i1 * D_DIM + d] +
                           bank[(size_t)i2 * D_DIM + d] +
                           bank[(size_t)i3 * D_DIM + d]);
        ograds[d] = v;
    }
}

// ---------------------------------------------------------------------------
// Kernel 5: pred_images = mean of 4 gathered image rows. Pure bandwidth.
// grid (N_FEAT, IMG_V4/256): blockIdx.x = n (fastest), blockIdx.y = slice.
// A wave of CTAs thus covers ONE 16KB slice of the bank across ALL features;
// the per-slice bank working set (2048 x 4KB per 256-thread chunk; ~32MB per
// concurrent window) stays L2-resident, so duplicate neighbor indices across
// features hit L2 instead of HBM.
// ---------------------------------------------------------------------------
__global__ void k_images(const float* __restrict__ imgs,
                         float* __restrict__ out)
{
    int n = blockIdx.x;
    int t = blockIdx.y * blockDim.x + threadIdx.x;   // float4 index, < IMG_V4

    int i0 = __ldg(&g_idx[n * K_NB + 0]);
    int i1 = __ldg(&g_idx[n * K_NB + 1]);
    int i2 = __ldg(&g_idx[n * K_NB + 2]);
    int i3 = __ldg(&g_idx[n * K_NB + 3]);

    const float4* iv = (const float4*)imgs;
    float4 a = __ldg(&iv[(size_t)i0 * IMG_V4 + t]);
    float4 b = __ldg(&iv[(size_t)i1 * IMG_V4 + t]);
    float4 c = __ldg(&iv[(size_t)i2 * IMG_V4 + t]);
    float4 d = __ldg(&iv[(size_t)i3 * IMG_V4 + t]);

    float4 r;
    r.x = 0.25f * (a.x + b.x + c.x + d.x);
    r.y = 0.25f * (a.y + b.y + c.y + d.y);
    r.z = 0.25f * (a.z + b.z + c.z + d.z);
    r.w = 0.25f * (a.w + b.w + c.w + d.w);

    float4* ov = (float4*)(out + O_IMAGES);
    ov[(size_t)n * IMG_V4 + t] = r;
}

// ---------------------------------------------------------------------------
extern "C" void kernel_launch(void* const* d_in, const int* in_sizes, int n_in,
                              void* d_out, int out_size)
{
    const float* feats  = (const float*)d_in[0];   // (256, 512)
    const float* bank   = (const float*)d_in[1];   // (2048, 512)
    const float* bprobs = (const float*)d_in[2];   // (2048, 1000)
    const float* imgs   = (const float*)d_in[3];   // (2048, 3, 224, 224)
    float* out = (float*)d_out;

    k_norms_bank<<<(Q_BANK * 32) / 256, 256>>>(bank);

    {
        dim3 grid(N_FEAT / 8, 8);                 // (32, 8) = 256 CTAs
        k_dist<<<grid, 256>>>(feats, bank);
    }
    k_topk<<<N_FEAT, 128>>>();
    k_probs_grads<<<N_FEAT, 256>>>(bank, bprobs, out);
    {
        dim3 grid(N_FEAT, IMG_V4 / 256);          // (256, 147), x = n fastest
        k_images<<<grid, 256>>>(imgs, out);
    }
}